// round 13
// baseline (speedup 1.0000x reference)
#include <cuda_runtime.h>

#define T_LEN  1024
#define NSTEP  1023
#define B_SZ   8192

typedef unsigned long long ull;

// scratch: time-major inputs
__device__ int   g_act_t[T_LEN * B_SZ];            // [t][b]
__device__ float g_rew_t[T_LEN * B_SZ];            // [t][b]

// ---------------- packed f32x2 helpers ----------------
__device__ __forceinline__ void ffma2(ull& d, ull a, ull b) {
    asm("fma.rn.f32x2 %0, %1, %2, %0;" : "+l"(d) : "l"(a), "l"(b));
}
__device__ __forceinline__ ull mul2(ull a, ull b) {
    ull r; asm("mul.rn.f32x2 %0, %1, %2;" : "=l"(r) : "l"(a), "l"(b)); return r;
}
__device__ __forceinline__ ull pack2(float x, float y) {
    ull r; asm("mov.b64 %0, {%1, %2};" : "=l"(r) : "f"(x), "f"(y)); return r;
}
__device__ __forceinline__ float2 unpack2(ull v) {
    float2 r; asm("mov.b64 {%0, %1}, %2;" : "=f"(r.x), "=f"(r.y) : "l"(v)); return r;
}
// input pre-scaled by 2*log2(e):  tanh = 1 - 2/(2^x' + 1)   (~1e-6 abs err)
__device__ __forceinline__ float tanh_pre(float xs) {
    float e, r;
    asm("ex2.approx.f32 %0, %1;" : "=f"(e) : "f"(xs));
    asm("rcp.approx.f32 %0, %1;" : "=f"(r) : "f"(e + 1.0f));
    return fmaf(-2.0f, r, 1.0f);
}
#define TANH_SC 2.8853900817779268f   // 2*log2(e)

// ---------------- transpose [B][T] -> [T][B]  +  zero(out) ----------------
__global__ void __launch_bounds__(256)
transpose_kernel(const int* __restrict__ act, const float* __restrict__ rew,
                 float* __restrict__ out) {
    const int tx = threadIdx.x, ty = threadIdx.y;
    if (blockIdx.z == 2) {
        const size_t base =
            ((size_t)blockIdx.y * gridDim.x + blockIdx.x) * (size_t)NSTEP;
        float4* o4 = (float4*)out;
        const float4 z = make_float4(0.f, 0.f, 0.f, 0.f);
        const int tid = ty * 32 + tx;
        for (int i = tid; i < NSTEP; i += 256) o4[base + i] = z;
        return;
    }
    __shared__ unsigned tile[32][33];
    const int tt = blockIdx.x * 32, tb = blockIdx.y * 32;
    const unsigned* src = (blockIdx.z == 0) ? (const unsigned*)act : (const unsigned*)rew;
    unsigned*       dst = (blockIdx.z == 0) ? (unsigned*)g_act_t  : (unsigned*)g_rew_t;
    #pragma unroll
    for (int i = 0; i < 32; i += 8)
        tile[ty + i][tx] = src[(long long)(tb + ty + i) * T_LEN + tt + tx];
    __syncthreads();
    #pragma unroll
    for (int i = 0; i < 32; i += 8)
        dst[(long long)(tt + ty + i) * B_SZ + tb + tx] = tile[tx][ty + i];
}

// ---------------- main recurrent kernel ----------------
// LANE-PER-ELEMENT with ROW-SPLIT. grid = 128 CTAs x 256 thr (8 warps).
// CTAs 0..63: reward; 64..127: action. Warp pair (p, h): pair p serves the 32
// elements b = cta*128 + p*32 + lane; warp h computes first-layer rows
// [16h, 16h+16). All weight reads are warp-uniform broadcasts. The two halves
// of the state are exchanged via double-buffered SMEM; second-layer partials
// via a parity-buffered slot; ONE __syncthreads per step.
__global__ void __launch_bounds__(256, 1)
memann_mod(const float* __restrict__ w_r1, const float* __restrict__ b_r1,
           const float* __restrict__ w_r2, const float* __restrict__ b_r2,
           const float* __restrict__ w_a1, const float* __restrict__ b_a1,
           const float* __restrict__ w_a2, const float* __restrict__ b_a2,
           float*       __restrict__ out)
{
    __shared__ __align__(16) ull w1u[32][16];        // prescaled rows, dim-pairs
    __shared__ __align__(16) ull bwu[32];            // reward {b', w0'}
    __shared__ __align__(16) ull w2u[16];            // w_r2 dim-pairs
    __shared__ __align__(16) ulonglong2 cba[16][4];  // action one-hot bias pairs
    __shared__ __align__(16) ull wa2u[4][16];        // w_a2 rows, dim-pairs
    // state: [parity][pair][lane][18] (stride 18 ull = 144B -> conflict-free)
    __shared__ __align__(16) ull sbuf[2][4][32][18];
    __shared__ float  pbufr[2][4][2][32];            // reward q-partials
    __shared__ __align__(8) float2 pbufa[2][4][2][32]; // action c-partials
    __shared__ float sc[5];                          // b_r2, b_a2[0..3]

    const int tid = threadIdx.x;
    const bool is_rew = blockIdx.x < 64;

    // ---- one-time staging ----
    if (is_rew) {
        #pragma unroll
        for (int k = 0; k < 2; k++) {
            const int i = tid * 2 + k;               // 512 ull
            const int r = i >> 4, p = i & 15;
            w1u[r][p] = pack2(w_r1[r * 33 + 1 + 2 * p] * TANH_SC,
                              w_r1[r * 33 + 2 + 2 * p] * TANH_SC);
        }
        if (tid < 32)
            bwu[tid] = pack2(b_r1[tid] * TANH_SC, w_r1[tid * 33] * TANH_SC);
        if (tid >= 32 && tid < 48) {
            const int p = tid - 32;
            w2u[p] = pack2(w_r2[2 * p], w_r2[2 * p + 1]);
        }
        if (tid == 48) sc[0] = b_r2[0];
    } else {
        #pragma unroll
        for (int k = 0; k < 2; k++) {
            const int i = tid * 2 + k;
            const int r = i >> 4, p = i & 15;
            w1u[r][p] = pack2(w_a1[r * 36 + 4 + 2 * p] * TANH_SC,
                              w_a1[r * 36 + 5 + 2 * p] * TANH_SC);
        }
        if (tid < 128) {
            const int j = tid >> 3, a = (tid >> 1) & 3, comp = tid & 1;
            const int row = 2 * j + comp;
            ((ull*)&cba[j][a])[comp] =
                pack2((w_a1[row * 36 + a] + b_a1[row]) * TANH_SC, 0.0f);
        }
        if (tid >= 128 && tid < 192) {
            const int k2 = (tid - 128) >> 4, p = (tid - 128) & 15;
            wa2u[k2][p] = pack2(w_a2[k2 * 32 + 2 * p], w_a2[k2 * 32 + 2 * p + 1]);
        }
        if (tid >= 192 && tid < 196) sc[1 + tid - 192] = b_a2[tid - 192];
    }
    // zero state buffer (both parities; only parity 0 strictly needed)
    for (int i = tid; i < 2 * 4 * 32 * 18; i += 256) (&sbuf[0][0][0][0])[i] = 0ull;
    __syncthreads();

    const int lane = tid & 31, wid = tid >> 5;
    const int pr = wid >> 1;           // element group (pair) 0..3
    const int h  = wid & 1;            // row half: rows [16h, 16h+16)
    const long long b =
        (long long)(is_rew ? blockIdx.x : blockIdx.x - 64) * 128 + pr * 32 + lane;
    const int*   ap = g_act_t + b;
    const float* rp = g_rew_t + b;
    float* op = out + (size_t)b * (NSTEP * 4) + 2 * h;   // this warp's 2 slots

    ull sh[8];                          // own half of state (dims [16h,16h+16))
    #pragma unroll
    for (int u = 0; u < 8; u++) sh[u] = 0ull;

    if (is_rew) {
        // ================= reward module =================
        const float br2 = sc[0];
        const int   kA = 2 * h, kB = 2 * h + 1;
        float qA = 0.f, qB = 0.f;
        int   a_cur = ap[0];
        float r_cur = rp[0];

        for (int t = 0; t < NSTEP; t++) {
            const int   a_nxt = ap[(t + 1) * B_SZ];
            const float r_nxt = rp[(t + 1) * B_SZ];

            // load partner half of state (written before previous sync)
            const ull* rb = &sbuf[t & 1][pr][lane][(1 - h) * 8];
            ull po[8];
            #pragma unroll
            for (int u = 0; u < 4; u++) {
                const ulonglong2 v = *(const ulonglong2*)&rb[2 * u];
                po[2 * u] = v.x; po[2 * u + 1] = v.y;
            }

            const ull rv = pack2(1.0f, r_cur);
            ull acc[16];
            #pragma unroll
            for (int r2 = 0; r2 < 8; r2++) {          // rows 16h+2r2, +1
                const ulonglong2 bw = *(const ulonglong2*)&bwu[16 * h + 2 * r2];
                acc[2 * r2]     = mul2(bw.x, rv);
                acc[2 * r2 + 1] = mul2(bw.y, rv);
            }
            #pragma unroll
            for (int pqo = 0; pqo < 4; pqo++) {        // own half first
                const int pq = 4 * h + pqo;
                const ull s0 = sh[2 * pqo], s1 = sh[2 * pqo + 1];
                #pragma unroll
                for (int r = 0; r < 16; r++) {
                    const ulonglong2 w = *(const ulonglong2*)&w1u[16 * h + r][2 * pq];
                    ffma2(acc[r], w.x, s0);
                    ffma2(acc[r], w.y, s1);
                }
            }
            #pragma unroll
            for (int pqo = 0; pqo < 4; pqo++) {        // partner half
                const int pq = 4 * (1 - h) + pqo;
                const ull s0 = po[2 * pqo], s1 = po[2 * pqo + 1];
                #pragma unroll
                for (int r = 0; r < 16; r++) {
                    const ulonglong2 w = *(const ulonglong2*)&w1u[16 * h + r][2 * pq];
                    ffma2(acc[r], w.x, s0);
                    ffma2(acc[r], w.y, s1);
                }
            }
            #pragma unroll
            for (int r2 = 0; r2 < 8; r2++) {
                const float2 u0 = unpack2(acc[2 * r2]);
                const float2 u1 = unpack2(acc[2 * r2 + 1]);
                sh[r2] = pack2(tanh_pre(u0.x + u0.y), tanh_pre(u1.x + u1.y));
            }

            // publish own new half
            ull* wb = &sbuf[(t + 1) & 1][pr][lane][h * 8];
            *(ulonglong2*)&wb[0] = make_ulonglong2(sh[0], sh[1]);
            *(ulonglong2*)&wb[2] = make_ulonglong2(sh[2], sh[3]);
            *(ulonglong2*)&wb[4] = make_ulonglong2(sh[4], sh[5]);
            *(ulonglong2*)&wb[6] = make_ulonglong2(sh[6], sh[7]);

            // own-dims q partial
            ull qa = 0ull;
            #pragma unroll
            for (int i = 0; i < 4; i++) {
                const ulonglong2 w = *(const ulonglong2*)&w2u[8 * h + 2 * i];
                ffma2(qa, w.x, sh[2 * i]);
                ffma2(qa, w.y, sh[2 * i + 1]);
            }
            const float2 qf = unpack2(qa);
            const float qp = qf.x + qf.y;
            pbufr[t & 1][pr][h][lane] = qp;

            __syncthreads();

            const float q_new = qp + pbufr[t & 1][pr][1 - h][lane] + br2;
            qA = (a_cur == kA) ? q_new : qA * 0.95f;
            qB = (a_cur == kB) ? q_new : qB * 0.95f;
            atomicAdd(op + (size_t)t * 4,     qA);
            atomicAdd(op + (size_t)t * 4 + 1, qB);

            a_cur = a_nxt; r_cur = r_nxt;
        }
    } else {
        // ================= action-history module =================
        const float baA = sc[1 + 2 * h];
        const float baB = sc[2 + 2 * h];
        int a_cur = ap[0];

        for (int t = 0; t < NSTEP; t++) {
            const int a_nxt = ap[(t + 1) * B_SZ];

            const ull* rb = &sbuf[t & 1][pr][lane][(1 - h) * 8];
            ull po[8];
            #pragma unroll
            for (int u = 0; u < 4; u++) {
                const ulonglong2 v = *(const ulonglong2*)&rb[2 * u];
                po[2 * u] = v.x; po[2 * u + 1] = v.y;
            }

            ull acc[16];
            #pragma unroll
            for (int r2 = 0; r2 < 8; r2++) {           // one-hot bias init
                const ulonglong2 cb = cba[8 * h + r2][a_cur];
                acc[2 * r2]     = cb.x;
                acc[2 * r2 + 1] = cb.y;
            }
            #pragma unroll
            for (int pqo = 0; pqo < 4; pqo++) {
                const int pq = 4 * h + pqo;
                const ull s0 = sh[2 * pqo], s1 = sh[2 * pqo + 1];
                #pragma unroll
                for (int r = 0; r < 16; r++) {
                    const ulonglong2 w = *(const ulonglong2*)&w1u[16 * h + r][2 * pq];
                    ffma2(acc[r], w.x, s0);
                    ffma2(acc[r], w.y, s1);
                }
            }
            #pragma unroll
            for (int pqo = 0; pqo < 4; pqo++) {
                const int pq = 4 * (1 - h) + pqo;
                const ull s0 = po[2 * pqo], s1 = po[2 * pqo + 1];
                #pragma unroll
                for (int r = 0; r < 16; r++) {
                    const ulonglong2 w = *(const ulonglong2*)&w1u[16 * h + r][2 * pq];
                    ffma2(acc[r], w.x, s0);
                    ffma2(acc[r], w.y, s1);
                }
            }
            #pragma unroll
            for (int r2 = 0; r2 < 8; r2++) {
                const float2 u0 = unpack2(acc[2 * r2]);
                const float2 u1 = unpack2(acc[2 * r2 + 1]);
                sh[r2] = pack2(tanh_pre(u0.x + u0.y), tanh_pre(u1.x + u1.y));
            }

            ull* wb = &sbuf[(t + 1) & 1][pr][lane][h * 8];
            *(ulonglong2*)&wb[0] = make_ulonglong2(sh[0], sh[1]);
            *(ulonglong2*)&wb[2] = make_ulonglong2(sh[2], sh[3]);
            *(ulonglong2*)&wb[4] = make_ulonglong2(sh[4], sh[5]);
            *(ulonglong2*)&wb[6] = make_ulonglong2(sh[6], sh[7]);

            // own-dims partials for all 4 outputs
            float cpart[4];
            #pragma unroll
            for (int k = 0; k < 4; k++) {
                ull ca = 0ull;
                #pragma unroll
                for (int i = 0; i < 4; i++) {
                    const ulonglong2 w = *(const ulonglong2*)&wa2u[k][8 * h + 2 * i];
                    ffma2(ca, w.x, sh[2 * i]);
                    ffma2(ca, w.y, sh[2 * i + 1]);
                }
                const float2 f = unpack2(ca);
                cpart[k] = f.x + f.y;
            }
            // publish partials for PARTNER's output components
            pbufa[t & 1][pr][h][lane] =
                make_float2(cpart[2 * (1 - h)], cpart[2 * (1 - h) + 1]);

            __syncthreads();

            const float2 other = pbufa[t & 1][pr][1 - h][lane];
            atomicAdd(op + (size_t)t * 4,     cpart[2 * h]     + other.x + baA);
            atomicAdd(op + (size_t)t * 4 + 1, cpart[2 * h + 1] + other.y + baB);

            a_cur = a_nxt;
        }
    }
}

extern "C" void kernel_launch(void* const* d_in, const int* in_sizes, int n_in,
                              void* d_out, int out_size) {
    (void)in_sizes; (void)n_in; (void)out_size;
    transpose_kernel<<<dim3(T_LEN / 32, B_SZ / 32, 3), dim3(32, 8)>>>(
        (const int*)d_in[0], (const float*)d_in[1], (float*)d_out);
    memann_mod<<<128, 256>>>(
        (const float*)d_in[2], (const float*)d_in[3],
        (const float*)d_in[4], (const float*)d_in[5],
        (const float*)d_in[6], (const float*)d_in[7],
        (const float*)d_in[8], (const float*)d_in[9],
        (float*)d_out);
}